// round 1
// baseline (speedup 1.0000x reference)
#include <cuda_runtime.h>
#include <math.h>

#define BB   8
#define CIN  512
#define COUT 1024
#define PP   2048
#define NH   8
#define DH   128

// Scratch: projected Q/K/V (pre-BN) and folded BN affine params.
__device__ float g_y[3][BB][COUT][PP];     // ~201 MB, [proj][b][o][p]  proj: 0=Q,1=K,2=V
__device__ float g_scale[3][COUT];
__device__ float g_shift[3][COUT];

// ---------------------------------------------------------------------------
// Stage 1: y[proj][b][o][p] = sum_c W[o][c] * x[b][c][p]
// 128x128 tile, K-chunk 8, 256 threads, 8x8 microtile.
// ---------------------------------------------------------------------------
__global__ __launch_bounds__(256) void gemm_qkv_kernel(
    const float* __restrict__ x,
    const float* __restrict__ Wq,
    const float* __restrict__ Wk,
    const float* __restrict__ Wv)
{
    int z = blockIdx.z;
    int proj = z >> 3, b = z & 7;
    const float* W = (proj == 0) ? Wq : ((proj == 1) ? Wk : Wv);
    const float* X = x + (size_t)b * CIN * PP;
    float* Y = &g_y[proj][b][0][0];

    __shared__ float As[8][128];   // [k][o]
    __shared__ float Bs[8][128];   // [k][p]

    int tid = threadIdx.x;
    int tx = tid & 15, ty = tid >> 4;
    int o0 = blockIdx.y * 128;
    int p0 = blockIdx.x * 128;

    float acc[8][8];
#pragma unroll
    for (int i = 0; i < 8; i++)
#pragma unroll
        for (int j = 0; j < 8; j++) acc[i][j] = 0.f;

    int a_row = tid >> 1;           // 0..127
    int a_col = (tid & 1) * 4;      // 0 or 4
    int b_row = tid >> 5;           // 0..7
    int b_col = (tid & 31) * 4;     // 0..124

    for (int kk = 0; kk < CIN; kk += 8) {
        float4 av = *(const float4*)&W[(size_t)(o0 + a_row) * CIN + kk + a_col];
        As[a_col + 0][a_row] = av.x;
        As[a_col + 1][a_row] = av.y;
        As[a_col + 2][a_row] = av.z;
        As[a_col + 3][a_row] = av.w;
        float4 bv = *(const float4*)&X[(size_t)(kk + b_row) * PP + p0 + b_col];
        *(float4*)&Bs[b_row][b_col] = bv;
        __syncthreads();
#pragma unroll
        for (int k = 0; k < 8; k++) {
            float4 t0 = *(float4*)&As[k][ty * 4];
            float4 t1 = *(float4*)&As[k][64 + ty * 4];
            float4 u0 = *(float4*)&Bs[k][tx * 4];
            float4 u1 = *(float4*)&Bs[k][64 + tx * 4];
            float a[8] = {t0.x, t0.y, t0.z, t0.w, t1.x, t1.y, t1.z, t1.w};
            float bb[8] = {u0.x, u0.y, u0.z, u0.w, u1.x, u1.y, u1.z, u1.w};
#pragma unroll
            for (int i = 0; i < 8; i++)
#pragma unroll
                for (int j = 0; j < 8; j++) acc[i][j] += a[i] * bb[j];
        }
        __syncthreads();
    }
#pragma unroll
    for (int i = 0; i < 8; i++) {
        int o = o0 + ((i < 4) ? (ty * 4 + i) : (64 + ty * 4 + (i - 4)));
        float* yr = &Y[(size_t)o * PP + p0];
        *(float4*)&yr[tx * 4]      = make_float4(acc[i][0], acc[i][1], acc[i][2], acc[i][3]);
        *(float4*)&yr[64 + tx * 4] = make_float4(acc[i][4], acc[i][5], acc[i][6], acc[i][7]);
    }
}

// ---------------------------------------------------------------------------
// Stage 2: per-channel batch stats over (b, p) -> folded affine scale/shift.
// One block per (channel, proj).
// ---------------------------------------------------------------------------
__global__ __launch_bounds__(256) void stats_kernel(
    const float* __restrict__ gq, const float* __restrict__ bq,
    const float* __restrict__ gk, const float* __restrict__ bk,
    const float* __restrict__ gv, const float* __restrict__ bv)
{
    int o = blockIdx.x;
    int proj = blockIdx.y;
    const float* base = &g_y[proj][0][o][0];
    float s = 0.f, s2 = 0.f;
    for (int t = threadIdx.x; t < BB * PP; t += 256) {
        int b = t >> 11, p = t & 2047;
        float v = base[(size_t)b * COUT * PP + p];
        s += v; s2 += v * v;
    }
    __shared__ float red0[256];
    __shared__ float red1[256];
    red0[threadIdx.x] = s; red1[threadIdx.x] = s2;
    __syncthreads();
    for (int st = 128; st > 0; st >>= 1) {
        if (threadIdx.x < st) {
            red0[threadIdx.x] += red0[threadIdx.x + st];
            red1[threadIdx.x] += red1[threadIdx.x + st];
        }
        __syncthreads();
    }
    if (threadIdx.x == 0) {
        const float invn = 1.f / (BB * PP);
        float mean = red0[0] * invn;
        float var  = red1[0] * invn - mean * mean;
        const float* g  = (proj == 0) ? gq : ((proj == 1) ? gk : gv);
        const float* be = (proj == 0) ? bq : ((proj == 1) ? bk : bv);
        float sc = g[o] * rsqrtf(var + 1e-5f);
        g_scale[proj][o] = sc;
        g_shift[proj][o] = be[o] - mean * sc;
    }
}

// ---------------------------------------------------------------------------
// Stage 3: fused flash-style attention per (b, h, i-tile of 64).
//   S[i][j] = sum_c K[c][i] V[c][j] / sqrt(128);  P = online-softmax rows
//   O[c][i] += P[i][j] Q[c][j];  out = O / l
// BN+LeakyReLU applied on the fly at tile loads.
// ---------------------------------------------------------------------------
#define QS_STRIDE 132
#define PS_STRIDE 65
#define ATTN_SMEM ((128*64*2 + 64*QS_STRIDE + 64*PS_STRIDE + 128) * 4)

__global__ __launch_bounds__(256) void attn_kernel(float* __restrict__ out)
{
    extern __shared__ float sm[];
    float* Ks   = sm;                        // [128][64]  (c-major)
    float* Vs   = Ks + 128 * 64;             // [128][64]
    float* Qs   = Vs + 128 * 64;             // [64][QS_STRIDE]  (j-major)
    float* Ps   = Qs + 64 * QS_STRIDE;       // [64][PS_STRIDE]  Ps[j][i]
    float* frow = Ps + 64 * PS_STRIDE;       // [64]
    float* lrow = frow + 64;                 // [64]

    int tid = threadIdx.x;
    int bh = blockIdx.y;
    int b = bh >> 3, h = bh & 7;
    int i0 = blockIdx.x * 64;
    int ch0 = h * DH;

    const float* Qy = &g_y[0][b][ch0][0];
    const float* Ky = &g_y[1][b][ch0][0];
    const float* Vy = &g_y[2][b][ch0][0];

    // Load K tile (BN + LeakyReLU folded)
    for (int t = tid; t < 128 * 64; t += 256) {
        int c = t >> 6, ii = t & 63;
        float v = Ky[(size_t)c * PP + i0 + ii];
        v = v * g_scale[1][ch0 + c] + g_shift[1][ch0 + c];
        Ks[t] = (v >= 0.f) ? v : 0.1f * v;
    }

    int tx = tid & 15;   // mapping1: j block (4*tx)
    int ty = tid >> 4;   // mapping1: i block (4*ty)
    int it2 = tid & 15;  // mapping2: i block (4*it2)
    int ct  = tid >> 4;  // mapping2: c block (8*ct)

    float m[4], l[4];
#pragma unroll
    for (int r = 0; r < 4; r++) { m[r] = -1e30f; l[r] = 0.f; }

    float O[8][4];
#pragma unroll
    for (int a = 0; a < 8; a++)
#pragma unroll
        for (int r = 0; r < 4; r++) O[a][r] = 0.f;

    const float inv_sqrt_dh = 0.08838834764831845f;

    for (int j0 = 0; j0 < PP; j0 += 64) {
        __syncthreads();   // prev GEMM2 / K load complete before overwriting Vs,Qs
        for (int t = tid; t < 128 * 64; t += 256) {
            int c = t >> 6, jj = t & 63;
            float v = Vy[(size_t)c * PP + j0 + jj];
            v = v * g_scale[2][ch0 + c] + g_shift[2][ch0 + c];
            Vs[t] = (v >= 0.f) ? v : 0.1f * v;
            float q = Qy[(size_t)c * PP + j0 + jj];
            q = q * g_scale[0][ch0 + c] + g_shift[0][ch0 + c];
            Qs[jj * QS_STRIDE + c] = (q >= 0.f) ? q : 0.1f * q;
        }
        __syncthreads();

        // --- S = K_i^T V_j (64x64x128) ---
        float s[4][4];
#pragma unroll
        for (int r = 0; r < 4; r++)
#pragma unroll
            for (int q = 0; q < 4; q++) s[r][q] = 0.f;

#pragma unroll 4
        for (int c = 0; c < 128; c++) {
            float4 kv = *(float4*)&Ks[c * 64 + 4 * ty];
            float4 vv = *(float4*)&Vs[c * 64 + 4 * tx];
            s[0][0] += kv.x * vv.x; s[0][1] += kv.x * vv.y; s[0][2] += kv.x * vv.z; s[0][3] += kv.x * vv.w;
            s[1][0] += kv.y * vv.x; s[1][1] += kv.y * vv.y; s[1][2] += kv.y * vv.z; s[1][3] += kv.y * vv.w;
            s[2][0] += kv.z * vv.x; s[2][1] += kv.z * vv.y; s[2][2] += kv.z * vv.z; s[2][3] += kv.z * vv.w;
            s[3][0] += kv.w * vv.x; s[3][1] += kv.w * vv.y; s[3][2] += kv.w * vv.z; s[3][3] += kv.w * vv.w;
        }

        // --- online softmax over rows (16-lane groups share a row set) ---
#pragma unroll
        for (int r = 0; r < 4; r++) {
#pragma unroll
            for (int q = 0; q < 4; q++) s[r][q] *= inv_sqrt_dh;
            float rm = fmaxf(fmaxf(s[r][0], s[r][1]), fmaxf(s[r][2], s[r][3]));
            rm = fmaxf(rm, __shfl_xor_sync(0xffffffffu, rm, 1));
            rm = fmaxf(rm, __shfl_xor_sync(0xffffffffu, rm, 2));
            rm = fmaxf(rm, __shfl_xor_sync(0xffffffffu, rm, 4));
            rm = fmaxf(rm, __shfl_xor_sync(0xffffffffu, rm, 8));
            float mnew = fmaxf(m[r], rm);
            float f = __expf(m[r] - mnew);
            float rs = 0.f;
#pragma unroll
            for (int q = 0; q < 4; q++) {
                float pv = __expf(s[r][q] - mnew);
                Ps[(4 * tx + q) * PS_STRIDE + 4 * ty + r] = pv;
                rs += pv;
            }
            rs += __shfl_xor_sync(0xffffffffu, rs, 1);
            rs += __shfl_xor_sync(0xffffffffu, rs, 2);
            rs += __shfl_xor_sync(0xffffffffu, rs, 4);
            rs += __shfl_xor_sync(0xffffffffu, rs, 8);
            l[r] = l[r] * f + rs;
            m[r] = mnew;
            if (tx == 0) frow[4 * ty + r] = f;
        }
        __syncthreads();

        // --- O = O*f + Q_j * P^T  (128x64 x 64) ---
        float f2[4];
#pragma unroll
        for (int r = 0; r < 4; r++) f2[r] = frow[4 * it2 + r];
#pragma unroll
        for (int a = 0; a < 8; a++)
#pragma unroll
            for (int r = 0; r < 4; r++) O[a][r] *= f2[r];

#pragma unroll 2
        for (int j = 0; j < 64; j++) {
            float p4[4];
#pragma unroll
            for (int r = 0; r < 4; r++) p4[r] = Ps[j * PS_STRIDE + 4 * it2 + r];
            float4 qa = *(float4*)&Qs[j * QS_STRIDE + 8 * ct];
            float4 qb = *(float4*)&Qs[j * QS_STRIDE + 8 * ct + 4];
            float q8[8] = {qa.x, qa.y, qa.z, qa.w, qb.x, qb.y, qb.z, qb.w};
#pragma unroll
            for (int a = 0; a < 8; a++)
#pragma unroll
                for (int r = 0; r < 4; r++) O[a][r] += q8[a] * p4[r];
        }
    }

    // --- finalize: divide by l, write out[b][ch0+c][i0+i] ---
    if (tx == 0) {
#pragma unroll
        for (int r = 0; r < 4; r++) lrow[4 * ty + r] = l[r];
    }
    __syncthreads();
    float inv[4];
#pragma unroll
    for (int r = 0; r < 4; r++) inv[r] = 1.f / lrow[4 * it2 + r];
#pragma unroll
    for (int a = 0; a < 8; a++) {
        int ch = ch0 + 8 * ct + a;
        float* op = &out[((size_t)b * COUT + ch) * PP + i0 + 4 * it2];
        *(float4*)op = make_float4(O[a][0] * inv[0], O[a][1] * inv[1],
                                   O[a][2] * inv[2], O[a][3] * inv[3]);
    }
}

// ---------------------------------------------------------------------------
extern "C" void kernel_launch(void* const* d_in, const int* in_sizes, int n_in,
                              void* d_out, int out_size)
{
    const float* x  = (const float*)d_in[0];
    const float* Wq = (const float*)d_in[1];
    const float* gq = (const float*)d_in[2];
    const float* bq = (const float*)d_in[3];
    const float* Wk = (const float*)d_in[4];
    const float* gk = (const float*)d_in[5];
    const float* bk = (const float*)d_in[6];
    const float* Wv = (const float*)d_in[7];
    const float* gv = (const float*)d_in[8];
    const float* bv = (const float*)d_in[9];
    float* out = (float*)d_out;

    gemm_qkv_kernel<<<dim3(PP / 128, COUT / 128, 3 * BB), 256>>>(x, Wq, Wk, Wv);
    stats_kernel<<<dim3(COUT, 3), 256>>>(gq, bq, gk, bk, gv, bv);

    cudaFuncSetAttribute(attn_kernel, cudaFuncAttributeMaxDynamicSharedMemorySize, ATTN_SMEM);
    attn_kernel<<<dim3(PP / 64, BB * NH), 256, ATTN_SMEM>>>(out);
}